// round 14
// baseline (speedup 1.0000x reference)
#include <cuda_runtime.h>
#include <cuda_bf16.h>
#include <math.h>
#include <cstdint>

#define BATCH 128
#define SEQ   4096
#define SD    5
#define HID   32
#define DIN   9
#define NTOK  (BATCH*SEQ)
#define TPB   128

__device__ float g_temp[NTOK];

typedef unsigned long long ull;

__device__ __forceinline__ ull pk(float lo, float hi) {
    ull r; asm("mov.b64 %0, {%1, %2};" : "=l"(r) : "f"(lo), "f"(hi)); return r;
}
__device__ __forceinline__ void upk(float& lo, float& hi, ull v) {
    asm("mov.b64 {%0, %1}, %2;" : "=f"(lo), "=f"(hi) : "l"(v));
}
__device__ __forceinline__ void ffma2(ull& d, ull a, ull b) {
    asm("fma.rn.f32x2 %0, %1, %2, %0;" : "+l"(d) : "l"(a), "l"(b));
}
__device__ __forceinline__ ull add2(ull a, ull b) {
    ull r; asm("add.rn.f32x2 %0, %1, %2;" : "=l"(r) : "l"(a), "l"(b)); return r;
}
__device__ __forceinline__ ull dup(float x) { return pk(x, x); }
__device__ __forceinline__ float tanh_apx(float x) {
    float y; asm("tanh.approx.f32 %0, %1;" : "=f"(y) : "f"(x)); return y;
}
__device__ __forceinline__ unsigned int pk_bf2(float lo, float hi) {
    unsigned int r;
    asm("cvt.rn.bf16x2.f32 %0, %1, %2;" : "=r"(r) : "f"(hi), "f"(lo));
    return r;
}
__device__ __forceinline__ uint32_t smem_u32(const void* p) {
    uint32_t a;
    asm("{ .reg .u64 t; cvta.to.shared.u64 t, %1; cvt.u32.u64 %0, t; }"
        : "=r"(a) : "l"(p));
    return a;
}
__device__ __forceinline__ void ldmatrix_x4(uint32_t& r0, uint32_t& r1,
                                            uint32_t& r2, uint32_t& r3,
                                            uint32_t addr) {
    asm volatile("ldmatrix.sync.aligned.m8n8.x4.shared.b16 {%0,%1,%2,%3}, [%4];"
                 : "=r"(r0), "=r"(r1), "=r"(r2), "=r"(r3) : "r"(addr));
}
__device__ __forceinline__ void mma_bf16(float* d, const uint32_t* a,
                                         uint32_t b0, uint32_t b1) {
    asm volatile(
        "mma.sync.aligned.m16n8k16.row.col.f32.bf16.bf16.f32 "
        "{%0,%1,%2,%3}, {%4,%5,%6,%7}, {%8,%9}, {%0,%1,%2,%3};"
        : "+f"(d[0]), "+f"(d[1]), "+f"(d[2]), "+f"(d[3])
        : "r"(a[0]), "r"(a[1]), "r"(a[2]), "r"(a[3]), "r"(b0), "r"(b1));
}

// -------------------------------------------------------------------------
// Kernel 1: per-batch-row inclusive cumsum of delta_x[..., 2] + init temp
// -------------------------------------------------------------------------
__global__ __launch_bounds__(1024) void cumsum_kernel(const float* __restrict__ dx) {
    __shared__ float wsum[32];
    const int b    = blockIdx.x;
    const int tid  = threadIdx.x;
    const int lane = tid & 31;
    const int wid  = tid >> 5;
    const float* row = dx + (size_t)b * SEQ * 6;

    const int s0 = tid * 4;
    float v0 = row[(s0 + 0) * 6 + 2];
    float v1 = row[(s0 + 1) * 6 + 2];
    float v2 = row[(s0 + 2) * 6 + 2];
    float v3 = row[(s0 + 3) * 6 + 2];
    float p0 = v0, p1 = p0 + v1, p2 = p1 + v2, p3 = p2 + v3;
    float tot = p3;

    float s = tot;
    #pragma unroll
    for (int off = 1; off < 32; off <<= 1) {
        float n = __shfl_up_sync(0xffffffffu, s, off);
        if (lane >= off) s += n;
    }
    if (lane == 31) wsum[wid] = s;
    __syncthreads();
    if (wid == 0) {
        float w = wsum[lane];
        #pragma unroll
        for (int off = 1; off < 32; off <<= 1) {
            float n = __shfl_up_sync(0xffffffffu, w, off);
            if (lane >= off) w += n;
        }
        wsum[lane] = w;
    }
    __syncthreads();

    float base = row[5] + (s - tot) + ((wid > 0) ? wsum[wid - 1] : 0.0f);
    float* outp = g_temp + (size_t)b * SEQ + s0;
    outp[0] = base + p0; outp[1] = base + p1;
    outp[2] = base + p2; outp[3] = base + p3;
}

// -------------------------------------------------------------------------
// Kernel 2: layer0 fp32 FFMA2 (1 token/thread) -> u bf16 smem tile ->
// ldmatrix -> per-warp mma.sync bf16 [32x32]@[32x64] -> fragment epilogue.
// -------------------------------------------------------------------------
#define UPITCH 80   // bytes per 32-col bf16 row (conflict-free for ldmatrix)

__global__ __launch_bounds__(TPB) void msc_main(
    const float* __restrict__ h_prev,  const float* __restrict__ delta_x,
    const float* __restrict__ Wa0,     const float* __restrict__ ba0,
    const float* __restrict__ Wb0,     const float* __restrict__ bb0,
    const float* __restrict__ Wa1,     const float* __restrict__ ba1,
    const float* __restrict__ Wb1,     const float* __restrict__ bb1,
    const float* __restrict__ W_alpha, const float* __restrict__ b_alpha,
    const float* __restrict__ W_beta,  const float* __restrict__ b_beta,
    const float* __restrict__ W_gamma, const float* __restrict__ b_gamma,
    const float* __restrict__ W_c,     const float* __restrict__ b_c,
    const float* __restrict__ W_out,
    float* __restrict__ out)
{
    __shared__ ull  sW0[DIN * HID];          // (wa0, wb0) pairs
    __shared__ ull  sB0[HID];                // (ba0, bb0)
    __shared__ ull  sH[HID][4];              // head weight pairs per j
    __shared__ ull  sAinit[4];
    __shared__ float sB1a[HID], sB1b[HID];
    __shared__ float sWout[SD];
    __shared__ __align__(16) unsigned char sU[128 * UPITCH];     // u bf16 tile
    __shared__ __align__(16) unsigned char sW1T[64 * UPITCH];    // W1^T bf16 [n][k]

    const int tid  = threadIdx.x;
    const int lane = tid & 31;
    const int w    = tid >> 5;
    const int q    = lane & 3;

    // ---- stage weights ----
    for (int idx = tid; idx < DIN * HID; idx += TPB)
        sW0[idx] = pk(Wa0[idx], Wb0[idx]);
    // W1T[n][k]: n<32 -> Wa1[k][n], n>=32 -> Wb1[k][n-32]
    for (int e = tid; e < 64 * HID; e += TPB) {
        int n = e >> 5, k = e & 31;
        float wv = (n < HID) ? Wa1[k * HID + n] : Wb1[k * HID + (n - HID)];
        *(__nv_bfloat16*)(sW1T + n * UPITCH + k * 2) = __float2bfloat16(wv);
    }
    if (tid < HID) {
        sB0[tid]  = pk(ba0[tid], bb0[tid]);
        sB1a[tid] = ba1[tid];
        sB1b[tid] = bb1[tid];
        sH[tid][0] = pk(W_alpha[tid],       W_beta[tid]);
        sH[tid][1] = pk(W_gamma[tid],       W_c[tid * SD + 0]);
        sH[tid][2] = pk(W_c[tid * SD + 1],  W_c[tid * SD + 2]);
        sH[tid][3] = pk(W_c[tid * SD + 3],  W_c[tid * SD + 4]);
    }
    if (tid == 0) {
        sAinit[0] = pk(b_alpha[0], b_beta[0]);
        sAinit[1] = pk(b_gamma[0], b_c[0]);
        sAinit[2] = pk(b_c[1],     b_c[2]);
        sAinit[3] = pk(b_c[3],     b_c[4]);
    }
    if (tid < SD) sWout[tid] = W_out[tid];
    __syncthreads();

    // ---- layer 0: token = blockIdx*128 + tid, gate-packed fp32 ----
    {
        const int t = blockIdx.x * TPB + tid;
        const float* hp  = h_prev  + (size_t)t * SD;
        const float* dxp = delta_x + (size_t)t * 6;
        const float d0 = dxp[0], d1 = dxp[1], d2 = dxp[2];
        float nrm = sqrtf(fmaf(d0, d0, fmaf(d1, d1, d2 * d2)));
        nrm = fmaxf(nrm, 1e-7f);
        const float inv = __fdividef(1.0f, nrm);

        ull l[DIN];
        l[0] = dup(hp[0]); l[1] = dup(hp[1]); l[2] = dup(hp[2]);
        l[3] = dup(hp[3]); l[4] = dup(hp[4]);
        l[5] = dup(g_temp[t]);
        l[6] = dup(d0 * inv); l[7] = dup(d1 * inv); l[8] = dup(d2 * inv);

        unsigned char* urow = sU + tid * UPITCH;
        #pragma unroll
        for (int jg = 0; jg < 4; jg++) {
            float u[8];
            #pragma unroll
            for (int jj = 0; jj < 8; jj++) {
                const int j = jg * 8 + jj;
                ull acc = sB0[j];
                #pragma unroll
                for (int i = 0; i < DIN; i++)
                    ffma2(acc, l[i], sW0[i * HID + j]);
                float a, b; upk(a, b, acc);
                u[jj] = tanh_apx(a) * tanh_apx(b);
            }
            uint4 pkd;
            pkd.x = pk_bf2(u[0], u[1]); pkd.y = pk_bf2(u[2], u[3]);
            pkd.z = pk_bf2(u[4], u[5]); pkd.w = pk_bf2(u[6], u[7]);
            *(uint4*)(urow + jg * 16) = pkd;
        }
    }
    __syncwarp();

    // ---- B fragments: W1T [64n x 32k] -> B[nt][kt][b0/b1] ----
    const uint32_t w1t_base = smem_u32(sW1T);
    uint32_t Bf[8][2][2];
    #pragma unroll
    for (int kt = 0; kt < 2; kt++) {
        #pragma unroll
        for (int g = 0; g < 4; g++) {
            const int m  = lane >> 3;          // matrix id 0..3
            const int nt = 2 * g + (m >> 1);
            const int kq = m & 1;
            uint32_t addr = w1t_base + (uint32_t)(nt * 8 + (lane & 7)) * UPITCH
                          + kt * 32 + kq * 16;
            ldmatrix_x4(Bf[2 * g][kt][0], Bf[2 * g][kt][1],
                        Bf[2 * g + 1][kt][0], Bf[2 * g + 1][kt][1], addr);
        }
    }

    // ---- A fragments: U rows w*32 .. w*32+31 ----
    const uint32_t u_base = smem_u32(sU);
    uint32_t Af[2][2][4];
    #pragma unroll
    for (int mt = 0; mt < 2; mt++) {
        #pragma unroll
        for (int kt = 0; kt < 2; kt++) {
            uint32_t addr = u_base
                + (uint32_t)(w * 32 + mt * 16 + (lane & 15)) * UPITCH
                + kt * 32 + (lane >> 4) * 16;
            ldmatrix_x4(Af[mt][kt][0], Af[mt][kt][1],
                        Af[mt][kt][2], Af[mt][kt][3], addr);
        }
    }

    // ---- MMA: d[mt][nt][4], 32 tokens x 64 outputs per warp ----
    float d[2][8][4];
    #pragma unroll
    for (int mt = 0; mt < 2; mt++)
        #pragma unroll
        for (int nt = 0; nt < 8; nt++)
            #pragma unroll
            for (int c = 0; c < 4; c++) d[mt][nt][c] = 0.0f;

    #pragma unroll
    for (int mt = 0; mt < 2; mt++) {
        #pragma unroll
        for (int nt = 0; nt < 8; nt++) {
            mma_bf16(d[mt][nt], Af[mt][0], Bf[nt][0][0], Bf[nt][0][1]);
            mma_bf16(d[mt][nt], Af[mt][1], Bf[nt][1][0], Bf[nt][1][1]);
        }
    }

    // ---- per-lane biases for its fixed j-set: j = (p>>1)*8 + 2q + (p&1) ----
    float myBa[8], myBb[8];
    #pragma unroll
    for (int p = 0; p < 8; p++) {
        const int j = (p >> 1) * 8 + 2 * q + (p & 1);
        myBa[p] = sB1a[j];
        myBb[p] = sB1b[j];
    }

    // ---- v = tanh*tanh per (slot, p) ----
    float vv[4][8];
    #pragma unroll
    for (int s = 0; s < 4; s++) {
        const int mt = s >> 1, co = (s & 1) * 2;
        #pragma unroll
        for (int p = 0; p < 8; p++) {
            const int nt = p >> 1, e = p & 1;
            const float apre = d[mt][nt][co + e]     + myBa[p];
            const float bpre = d[mt][nt + 4][co + e] + myBb[p];
            vv[s][p] = tanh_apx(apre) * tanh_apx(bpre);
        }
    }

    // ---- heads: partial sums per lane over its 8 j ----
    ull H[4][4];
    #pragma unroll
    for (int s = 0; s < 4; s++)
        #pragma unroll
        for (int m = 0; m < 4; m++) H[s][m] = 0ULL;

    #pragma unroll
    for (int p = 0; p < 8; p++) {
        const int j = (p >> 1) * 8 + 2 * q + (p & 1);
        const ull hw0 = sH[j][0], hw1 = sH[j][1], hw2 = sH[j][2], hw3 = sH[j][3];
        #pragma unroll
        for (int s = 0; s < 4; s++) {
            const ull vd = dup(vv[s][p]);
            ffma2(H[s][0], vd, hw0);
            ffma2(H[s][1], vd, hw1);
            ffma2(H[s][2], vd, hw2);
            ffma2(H[s][3], vd, hw3);
        }
    }

    // ---- butterfly-reduce over the 4-lane column group (q) ----
    #pragma unroll
    for (int mask = 1; mask <= 2; mask <<= 1) {
        #pragma unroll
        for (int s = 0; s < 4; s++)
            #pragma unroll
            for (int m = 0; m < 4; m++) {
                ull o = __shfl_xor_sync(0xffffffffu, H[s][m], mask);
                H[s][m] = add2(H[s][m], o);
            }
    }

    // ---- tail: lane handles token slot q ----
    {
        const int r = ((q >> 1) * 16) + ((q & 1) * 8) + (lane >> 2);
        const int t = blockIdx.x * TPB + w * 32 + r;

        const ull Hf0 = add2(H[q][0], sAinit[0]);
        const ull Hf1 = add2(H[q][1], sAinit[1]);
        const ull Hf2 = add2(H[q][2], sAinit[2]);
        const ull Hf3 = add2(H[q][3], sAinit[3]);

        float sa, sb, sg, c0, c1, c2, c3, c4;
        upk(sa, sb, Hf0);
        upk(sg, c0, Hf1);
        upk(c1, c2, Hf2);
        upk(c3, c4, Hf3);

        const float* dxp = delta_x + (size_t)t * 6;
        const float* hp  = h_prev  + (size_t)t * SD;
        const float d0 = dxp[0], d1 = dxp[1], d2 = dxp[2];

        const float alpha = __expf(sa);
        const float beta  = __expf(sb);
        const float gamma = __expf(sg);
        const float zarg = fmaf(alpha, fabsf(d0), fmaf(beta, d1, gamma * fabsf(d2)));
        const float z = 1.0f - __expf(-zarg);

        float c[SD] = { c0, c1, c2, c3, c4 };
        float sigma = 0.0f;
        #pragma unroll
        for (int dd = 0; dd < SD; dd++) {
            const float hv = hp[dd];
            const float cn = tanh_apx(c[dd]);
            const float hn = fmaf(z, cn - hv, hv);
            out[(size_t)t * SD + dd] = hn;
            sigma = fmaf(hn, sWout[dd], sigma);
        }
        out[(size_t)NTOK * SD + t] = sigma;
    }
}

extern "C" void kernel_launch(void* const* d_in, const int* in_sizes, int n_in,
                              void* d_out, int out_size) {
    const float* h_prev  = (const float*)d_in[0];
    const float* delta_x = (const float*)d_in[1];
    const float* Wa0     = (const float*)d_in[2];
    const float* ba0     = (const float*)d_in[3];
    const float* Wb0     = (const float*)d_in[4];
    const float* bb0     = (const float*)d_in[5];
    const float* Wa1     = (const float*)d_in[6];
    const float* ba1     = (const float*)d_in[7];
    const float* Wb1     = (const float*)d_in[8];
    const float* bb1     = (const float*)d_in[9];
    const float* W_alpha = (const float*)d_in[10];
    const float* b_alpha = (const float*)d_in[11];
    const float* W_beta  = (const float*)d_in[12];
    const float* b_beta  = (const float*)d_in[13];
    const float* W_gamma = (const float*)d_in[14];
    const float* b_gamma = (const float*)d_in[15];
    const float* W_c     = (const float*)d_in[16];
    const float* b_c     = (const float*)d_in[17];
    const float* W_out   = (const float*)d_in[18];
    float* out = (float*)d_out;

    cumsum_kernel<<<BATCH, 1024>>>(delta_x);
    msc_main<<<NTOK / TPB, TPB>>>(h_prev, delta_x,
                                  Wa0, ba0, Wb0, bb0,
                                  Wa1, ba1, Wb1, bb1,
                                  W_alpha, b_alpha, W_beta, b_beta,
                                  W_gamma, b_gamma, W_c, b_c, W_out,
                                  out);
}

// round 15
// speedup vs baseline: 1.3121x; 1.3121x over previous
#include <cuda_runtime.h>
#include <cuda_bf16.h>
#include <math.h>
#include <cstdint>

#define BATCH 128
#define SEQ   4096
#define SD    5
#define HID   32
#define DIN   9
#define NTOK  (BATCH*SEQ)
#define TPB   128
#define TOKS_PER_BLOCK 512   // 4 per thread

__device__ float g_temp[NTOK];

typedef unsigned long long ull;

__device__ __forceinline__ ull pk(float lo, float hi) {
    ull r; asm("mov.b64 %0, {%1, %2};" : "=l"(r) : "f"(lo), "f"(hi)); return r;
}
__device__ __forceinline__ void upk(float& lo, float& hi, ull v) {
    asm("mov.b64 {%0, %1}, %2;" : "=f"(lo), "=f"(hi) : "l"(v));
}
__device__ __forceinline__ void ffma2(ull& d, ull a, ull b) {
    asm("fma.rn.f32x2 %0, %1, %2, %0;" : "+l"(d) : "l"(a), "l"(b));
}
__device__ __forceinline__ ull add2(ull a, ull b) {
    ull r; asm("add.rn.f32x2 %0, %1, %2;" : "=l"(r) : "l"(a), "l"(b)); return r;
}
__device__ __forceinline__ ull dup(float x) { return pk(x, x); }
__device__ __forceinline__ float tanh_apx(float x) {
    float y; asm("tanh.approx.f32 %0, %1;" : "=f"(y) : "f"(x)); return y;
}
__device__ __forceinline__ unsigned int pk_bf2(float lo, float hi) {
    unsigned int r;
    asm("cvt.rn.bf16x2.f32 %0, %1, %2;" : "=r"(r) : "f"(hi), "f"(lo));
    return r;
}
__device__ __forceinline__ uint32_t smem_u32(const void* p) {
    uint32_t a;
    asm("{ .reg .u64 t; cvta.to.shared.u64 t, %1; cvt.u32.u64 %0, t; }"
        : "=r"(a) : "l"(p));
    return a;
}
__device__ __forceinline__ void ldmatrix_x4(uint32_t& r0, uint32_t& r1,
                                            uint32_t& r2, uint32_t& r3,
                                            uint32_t addr) {
    asm volatile("ldmatrix.sync.aligned.m8n8.x4.shared.b16 {%0,%1,%2,%3}, [%4];"
                 : "=r"(r0), "=r"(r1), "=r"(r2), "=r"(r3) : "r"(addr));
}
__device__ __forceinline__ void mma_bf16(float* d, const uint32_t* a,
                                         uint32_t b0, uint32_t b1) {
    asm volatile(
        "mma.sync.aligned.m16n8k16.row.col.f32.bf16.bf16.f32 "
        "{%0,%1,%2,%3}, {%4,%5,%6,%7}, {%8,%9}, {%0,%1,%2,%3};"
        : "+f"(d[0]), "+f"(d[1]), "+f"(d[2]), "+f"(d[3])
        : "r"(a[0]), "r"(a[1]), "r"(a[2]), "r"(a[3]), "r"(b0), "r"(b1));
}

// -------------------------------------------------------------------------
// Kernel 1: per-batch-row inclusive cumsum of delta_x[..., 2] + init temp
// -------------------------------------------------------------------------
__global__ __launch_bounds__(1024) void cumsum_kernel(const float* __restrict__ dx) {
    __shared__ float wsum[32];
    const int b    = blockIdx.x;
    const int tid  = threadIdx.x;
    const int lane = tid & 31;
    const int wid  = tid >> 5;
    const float* row = dx + (size_t)b * SEQ * 6;

    const int s0 = tid * 4;
    float v0 = row[(s0 + 0) * 6 + 2];
    float v1 = row[(s0 + 1) * 6 + 2];
    float v2 = row[(s0 + 2) * 6 + 2];
    float v3 = row[(s0 + 3) * 6 + 2];
    float p0 = v0, p1 = p0 + v1, p2 = p1 + v2, p3 = p2 + v3;
    float tot = p3;

    float s = tot;
    #pragma unroll
    for (int off = 1; off < 32; off <<= 1) {
        float n = __shfl_up_sync(0xffffffffu, s, off);
        if (lane >= off) s += n;
    }
    if (lane == 31) wsum[wid] = s;
    __syncthreads();
    if (wid == 0) {
        float w = wsum[lane];
        #pragma unroll
        for (int off = 1; off < 32; off <<= 1) {
            float n = __shfl_up_sync(0xffffffffu, w, off);
            if (lane >= off) w += n;
        }
        wsum[lane] = w;
    }
    __syncthreads();

    float base = row[5] + (s - tot) + ((wid > 0) ? wsum[wid - 1] : 0.0f);
    float* outp = g_temp + (size_t)b * SEQ + s0;
    outp[0] = base + p0; outp[1] = base + p1;
    outp[2] = base + p2; outp[3] = base + p3;
}

// -------------------------------------------------------------------------
// Kernel 2: 512 tokens/block.
//   layer0: T=4 token-packed fp32 FFMA2 (R13) -> u bf16 tile (40KB smem)
//   layer1: per-warp mma.sync bf16, W1 split hi+lo (precision), 4 tiles/warp
//   epilogue: R14 fragment epilogue
// -------------------------------------------------------------------------
#define UPITCH 80   // bytes per 32-col bf16 row; conflict-free ldmatrix + STS.128

// dynamic smem offsets
#define SM_U     0                         // 512*80 = 40960
#define SM_W1TH  40960                     // 64*80 = 5120
#define SM_W1TL  46080                     // 5120
#define SM_W0    51200                     // 288 ulonglong2 = 4608
#define SM_B0    55808                     // 32 ulonglong2 = 512
#define SM_H     56320                     // 32*4 ull = 1024
#define SM_B1A   57344                     // 32 f
#define SM_B1B   57472                     // 32 f
#define SM_AINIT 57600                     // 4 ull
#define SM_WOUT  57632                     // 5 f
#define SM_TOTAL 57728

__global__ __launch_bounds__(TPB) void msc_main(
    const float* __restrict__ h_prev,  const float* __restrict__ delta_x,
    const float* __restrict__ Wa0,     const float* __restrict__ ba0,
    const float* __restrict__ Wb0,     const float* __restrict__ bb0,
    const float* __restrict__ Wa1,     const float* __restrict__ ba1,
    const float* __restrict__ Wb1,     const float* __restrict__ bb1,
    const float* __restrict__ W_alpha, const float* __restrict__ b_alpha,
    const float* __restrict__ W_beta,  const float* __restrict__ b_beta,
    const float* __restrict__ W_gamma, const float* __restrict__ b_gamma,
    const float* __restrict__ W_c,     const float* __restrict__ b_c,
    const float* __restrict__ W_out,
    float* __restrict__ out)
{
    extern __shared__ __align__(16) unsigned char smem[];
    ulonglong2* sW0   = (ulonglong2*)(smem + SM_W0);
    ulonglong2* sB0   = (ulonglong2*)(smem + SM_B0);
    ull*        sH    = (ull*)(smem + SM_H);
    float*      sB1a  = (float*)(smem + SM_B1A);
    float*      sB1b  = (float*)(smem + SM_B1B);
    ull*        sAin  = (ull*)(smem + SM_AINIT);
    float*      sWout = (float*)(smem + SM_WOUT);

    const int tid  = threadIdx.x;
    const int lane = tid & 31;
    const int w    = tid >> 5;
    const int q    = lane & 3;

    // ---- stage weights ----
    for (int idx = tid; idx < DIN * HID; idx += TPB) {
        float wa = Wa0[idx], wb = Wb0[idx];
        sW0[idx] = make_ulonglong2(pk(wa, wa), pk(wb, wb));
    }
    // W1T hi/lo: row n (0..63), col k (0..31); n<32 -> Wa1[k][n], else Wb1
    for (int e = tid; e < 64 * HID; e += TPB) {
        int n = e >> 5, k = e & 31;
        float wv = (n < HID) ? Wa1[k * HID + n] : Wb1[k * HID + (n - HID)];
        __nv_bfloat16 bh = __float2bfloat16(wv);
        float wl = wv - __bfloat162float(bh);
        __nv_bfloat16 bl = __float2bfloat16(wl);
        *(__nv_bfloat16*)(smem + SM_W1TH + n * UPITCH + k * 2) = bh;
        *(__nv_bfloat16*)(smem + SM_W1TL + n * UPITCH + k * 2) = bl;
    }
    if (tid < HID) {
        sB0[tid]  = make_ulonglong2(dup(ba0[tid]), dup(bb0[tid]));
        sB1a[tid] = ba1[tid];
        sB1b[tid] = bb1[tid];
        sH[tid * 4 + 0] = pk(W_alpha[tid],       W_beta[tid]);
        sH[tid * 4 + 1] = pk(W_gamma[tid],       W_c[tid * SD + 0]);
        sH[tid * 4 + 2] = pk(W_c[tid * SD + 1],  W_c[tid * SD + 2]);
        sH[tid * 4 + 3] = pk(W_c[tid * SD + 3],  W_c[tid * SD + 4]);
    }
    if (tid == 0) {
        sAin[0] = pk(b_alpha[0], b_beta[0]);
        sAin[1] = pk(b_gamma[0], b_c[0]);
        sAin[2] = pk(b_c[1],     b_c[2]);
        sAin[3] = pk(b_c[3],     b_c[4]);
    }
    if (tid < SD) sWout[tid] = W_out[tid];
    __syncthreads();

    const int tb = blockIdx.x * TOKS_PER_BLOCK;

    // ---- per-token inputs, token-packed f32x2 pairs (tokens tb + k*128 + tid)
    ull l01[DIN], l23[DIN];
    {
        float lv[4][DIN];
        #pragma unroll
        for (int k = 0; k < 4; k++) {
            const int t = tb + k * TPB + tid;
            const float* hp  = h_prev  + (size_t)t * SD;
            const float* dxp = delta_x + (size_t)t * 6;
            #pragma unroll
            for (int d = 0; d < SD; d++) lv[k][d] = hp[d];
            float d0 = dxp[0], d1 = dxp[1], d2 = dxp[2];
            float nrm = sqrtf(fmaf(d0, d0, fmaf(d1, d1, d2 * d2)));
            nrm = fmaxf(nrm, 1e-7f);
            float inv = __fdividef(1.0f, nrm);
            lv[k][5] = g_temp[t];
            lv[k][6] = d0 * inv; lv[k][7] = d1 * inv; lv[k][8] = d2 * inv;
        }
        #pragma unroll
        for (int d = 0; d < DIN; d++) {
            l01[d] = pk(lv[0][d], lv[1][d]);
            l23[d] = pk(lv[2][d], lv[3][d]);
        }
    }

    // ---- layer 0: T=4 gate-per-accum fp32, u -> bf16 tile rows k*128+tid ----
    #pragma unroll 1
    for (int jg = 0; jg < 4; jg++) {
        float uv[4][8];
        #pragma unroll
        for (int jj = 0; jj < 8; jj++) {
            const int j = jg * 8 + jj;
            ulonglong2 bb = sB0[j];
            ull a01 = bb.x, a23 = bb.x;
            ull g01 = bb.y, g23 = bb.y;
            #pragma unroll
            for (int i = 0; i < DIN; i++) {
                ulonglong2 wp = sW0[i * HID + j];
                ffma2(a01, l01[i], wp.x);
                ffma2(a23, l23[i], wp.x);
                ffma2(g01, l01[i], wp.y);
                ffma2(g23, l23[i], wp.y);
            }
            float x0, x1, x2, x3, y0, y1, y2, y3;
            upk(x0, x1, a01); upk(x2, x3, a23);
            upk(y0, y1, g01); upk(y2, y3, g23);
            uv[0][jj] = tanh_apx(x0) * tanh_apx(y0);
            uv[1][jj] = tanh_apx(x1) * tanh_apx(y1);
            uv[2][jj] = tanh_apx(x2) * tanh_apx(y2);
            uv[3][jj] = tanh_apx(x3) * tanh_apx(y3);
        }
        #pragma unroll
        for (int k = 0; k < 4; k++) {
            uint4 pkd;
            pkd.x = pk_bf2(uv[k][0], uv[k][1]);
            pkd.y = pk_bf2(uv[k][2], uv[k][3]);
            pkd.z = pk_bf2(uv[k][4], uv[k][5]);
            pkd.w = pk_bf2(uv[k][6], uv[k][7]);
            *(uint4*)(smem + SM_U + (k * TPB + tid) * UPITCH + jg * 16) = pkd;
        }
    }
    __syncwarp();   // warp w's MMA rows are written by warp w only

    const uint32_t u_base   = smem_u32(smem + SM_U);
    const uint32_t w1h_base = smem_u32(smem + SM_W1TH);
    const uint32_t w1l_base = smem_u32(smem + SM_W1TL);

    // ---- per-lane head biases/weights (fixed j-set) ----
    float myBa[8], myBb[8];
    #pragma unroll
    for (int p = 0; p < 8; p++) {
        const int j = (p >> 1) * 8 + 2 * q + (p & 1);
        myBa[p] = sB1a[j];
        myBb[p] = sB1b[j];
    }

    // ---- 4 tiles of 32 tokens per warp ----
    #pragma unroll 1
    for (int T = 0; T < 4; T++) {
        // A fragments: rows T*128 + w*32 + ...
        uint32_t Af[2][2][4];
        #pragma unroll
        for (int mt = 0; mt < 2; mt++) {
            #pragma unroll
            for (int kt = 0; kt < 2; kt++) {
                uint32_t addr = u_base
                    + (uint32_t)(T * TPB + w * 32 + mt * 16 + (lane & 15)) * UPITCH
                    + kt * 32 + (lane >> 4) * 16;
                ldmatrix_x4(Af[mt][kt][0], Af[mt][kt][1],
                            Af[mt][kt][2], Af[mt][kt][3], addr);
            }
        }
        // B fragments hi/lo
        uint32_t Bh[8][2][2], Bl[8][2][2];
        #pragma unroll
        for (int kt = 0; kt < 2; kt++) {
            #pragma unroll
            for (int g = 0; g < 4; g++) {
                const int m  = lane >> 3;
                const int nt = 2 * g + (m >> 1);
                const int kq = m & 1;
                uint32_t off = (uint32_t)(nt * 8 + (lane & 7)) * UPITCH
                             + kt * 32 + kq * 16;
                ldmatrix_x4(Bh[2 * g][kt][0], Bh[2 * g][kt][1],
                            Bh[2 * g + 1][kt][0], Bh[2 * g + 1][kt][1],
                            w1h_base + off);
                ldmatrix_x4(Bl[2 * g][kt][0], Bl[2 * g][kt][1],
                            Bl[2 * g + 1][kt][0], Bl[2 * g + 1][kt][1],
                            w1l_base + off);
            }
        }

        // MMA: D = A*Bhi + A*Blo
        float d[2][8][4];
        #pragma unroll
        for (int mt = 0; mt < 2; mt++)
            #pragma unroll
            for (int nt = 0; nt < 8; nt++) {
                #pragma unroll
                for (int c = 0; c < 4; c++) d[mt][nt][c] = 0.0f;
                mma_bf16(d[mt][nt], Af[mt][0], Bh[nt][0][0], Bh[nt][0][1]);
                mma_bf16(d[mt][nt], Af[mt][1], Bh[nt][1][0], Bh[nt][1][1]);
                mma_bf16(d[mt][nt], Af[mt][0], Bl[nt][0][0], Bl[nt][0][1]);
                mma_bf16(d[mt][nt], Af[mt][1], Bl[nt][1][0], Bl[nt][1][1]);
            }

        // v = tanh*tanh per (slot, p)
        float vv[4][8];
        #pragma unroll
        for (int s = 0; s < 4; s++) {
            const int mt = s >> 1, co = (s & 1) * 2;
            #pragma unroll
            for (int p = 0; p < 8; p++) {
                const int nt = p >> 1, e = p & 1;
                const float apre = d[mt][nt][co + e]     + myBa[p];
                const float bpre = d[mt][nt + 4][co + e] + myBb[p];
                vv[s][p] = tanh_apx(apre) * tanh_apx(bpre);
            }
        }

        // heads partial sums
        ull H[4][4];
        #pragma unroll
        for (int s = 0; s < 4; s++)
            #pragma unroll
            for (int m = 0; m < 4; m++) H[s][m] = 0ULL;

        #pragma unroll
        for (int p = 0; p < 8; p++) {
            const int j = (p >> 1) * 8 + 2 * q + (p & 1);
            const ull hw0 = sH[j * 4 + 0], hw1 = sH[j * 4 + 1];
            const ull hw2 = sH[j * 4 + 2], hw3 = sH[j * 4 + 3];
            #pragma unroll
            for (int s = 0; s < 4; s++) {
                const ull vd = dup(vv[s][p]);
                ffma2(H[s][0], vd, hw0);
                ffma2(H[s][1], vd, hw1);
                ffma2(H[s][2], vd, hw2);
                ffma2(H[s][3], vd, hw3);
            }
        }

        // butterfly reduce over 4-lane column group
        #pragma unroll
        for (int mask = 1; mask <= 2; mask <<= 1) {
            #pragma unroll
            for (int s = 0; s < 4; s++)
                #pragma unroll
                for (int m = 0; m < 4; m++) {
                    ull o = __shfl_xor_sync(0xffffffffu, H[s][m], mask);
                    H[s][m] = add2(H[s][m], o);
                }
        }

        // tail: lane handles token slot q
        {
            const int r = ((q >> 1) * 16) + ((q & 1) * 8) + (lane >> 2);
            const int t = tb + T * TPB + w * 32 + r;

            const ull Hf0 = add2(H[q][0], sAin[0]);
            const ull Hf1 = add2(H[q][1], sAin[1]);
            const ull Hf2 = add2(H[q][2], sAin[2]);
            const ull Hf3 = add2(H[q][3], sAin[3]);

            float sa, sb, sg, c0, c1, c2, c3, c4;
            upk(sa, sb, Hf0);
            upk(sg, c0, Hf1);
            upk(c1, c2, Hf2);
            upk(c3, c4, Hf3);

            const float* dxp = delta_x + (size_t)t * 6;
            const float* hp  = h_prev  + (size_t)t * SD;
            const float d0 = dxp[0], d1 = dxp[1], d2 = dxp[2];

            const float alpha = __expf(sa);
            const float beta  = __expf(sb);
            const float gamma = __expf(sg);
            const float zarg = fmaf(alpha, fabsf(d0), fmaf(beta, d1, gamma * fabsf(d2)));
            const float z = 1.0f - __expf(-zarg);

            float c[SD] = { c0, c1, c2, c3, c4 };
            float sigma = 0.0f;
            #pragma unroll
            for (int dd = 0; dd < SD; dd++) {
                const float hv = hp[dd];
                const float cn = tanh_apx(c[dd]);
                const float hn = fmaf(z, cn - hv, hv);
                out[(size_t)t * SD + dd] = hn;
                sigma = fmaf(hn, sWout[dd], sigma);
            }
            out[(size_t)NTOK * SD + t] = sigma;
        }
    }
}

extern "C" void kernel_launch(void* const* d_in, const int* in_sizes, int n_in,
                              void* d_out, int out_size) {
    const float* h_prev  = (const float*)d_in[0];
    const float* delta_x = (const float*)d_in[1];
    const float* Wa0     = (const float*)d_in[2];
    const float* ba0     = (const float*)d_in[3];
    const float* Wb0     = (const float*)d_in[4];
    const float* bb0     = (const float*)d_in[5];
    const float* Wa1     = (const float*)d_in[6];
    const float* ba1     = (const float*)d_in[7];
    const float* Wb1     = (const float*)d_in[8];
    const float* bb1     = (const float*)d_in[9];
    const float* W_alpha = (const float*)d_in[10];
    const float* b_alpha = (const float*)d_in[11];
    const float* W_beta  = (const float*)d_in[12];
    const float* b_beta  = (const float*)d_in[13];
    const float* W_gamma = (const float*)d_in[14];
    const float* b_gamma = (const float*)d_in[15];
    const float* W_c     = (const float*)d_in[16];
    const float* b_c     = (const float*)d_in[17];
    const float* W_out   = (const float*)d_in[18];
    float* out = (float*)d_out;

    static int attr_set = 0;
    cudaFuncSetAttribute(msc_main, cudaFuncAttributeMaxDynamicSharedMemorySize,
                         SM_TOTAL);
    (void)attr_set;

    cumsum_kernel<<<BATCH, 1024>>>(delta_x);
    msc_main<<<NTOK / TOKS_PER_BLOCK, TPB, SM_TOTAL>>>(
        h_prev, delta_x,
        Wa0, ba0, Wb0, bb0,
        Wa1, ba1, Wb1, bb1,
        W_alpha, b_alpha, W_beta, b_beta,
        W_gamma, b_gamma, W_c, b_c, W_out,
        out);
}